// round 4
// baseline (speedup 1.0000x reference)
#include <cuda_runtime.h>
#include <cstdint>

// Problem constants (B=16, H=W=1024)
#define HW_SHIFT 20            // H*W = 1<<20
#define W_SHIFT  10            // W = 1024
#define W_DIM    1024
#define HW_DIM   (1 << HW_SHIFT)
#define TOTAL_PIX (16 * HW_DIM)        // 16,777,216
#define PIX_PER_THREAD 4
#define THREADS 256
#define BLOCKS (TOTAL_PIX / (PIX_PER_THREAD * THREADS))   // 16384
#define EPSF 1e-7f

__global__ void zero_out_kernel(float* out) {
    if (threadIdx.x == 0) out[0] = 0.0f;
}

__global__ __launch_bounds__(THREADS, 1)
void confidence_loss_kernel(const float* __restrict__ o_f,
                            const int* __restrict__ target,
                            float* __restrict__ out) {
    const long long tid  = (long long)blockIdx.x * THREADS + threadIdx.x;
    const long long base = tid * PIX_PER_THREAD;          // first pixel index

    const int b   = (int)(base >> HW_SHIFT);
    const int rem = (int)(base & (HW_DIM - 1));
    const int i   = rem >> W_SHIFT;
    const int j   = rem & (W_DIM - 1);

    // Vectorized loads: channel planes are [B,3,H,W] contiguous.
    const float* p0 = o_f + (size_t)b * 3 * HW_DIM + rem;     // channel 0
    const float4 f0 = *(const float4*)(p0);
    const float4 f1 = *(const float4*)(p0 + HW_DIM);          // channel 1
    const float4 f2 = *(const float4*)(p0 + 2 * HW_DIM);      // channel 2

    // target is int32 on device (JAX x64 disabled downcasts int64 -> int32)
    const int* tbase = target + (size_t)b * HW_DIM;
    const int4 t4 = *(const int4*)(tbase + rem);

    float o0v[4] = {f0.x, f0.y, f0.z, f0.w};
    float o1v[4] = {f1.x, f1.y, f1.z, f1.w};
    float fv [4] = {f2.x, f2.y, f2.z, f2.w};
    int   tv [4] = {t4.x, t4.y, t4.z, t4.w};

    float acc = 0.0f;

#pragma unroll
    for (int k = 0; k < PIX_PER_THREAD; k++) {
        const int jj = j + k;

        int x = (int)floorf(o0v[k] + (float)jj);
        int y = (int)floorf(o1v[k] + (float)i);
        x = min(max(x, 0), W_DIM - 1);
        y = min(max(y, 0), W_DIM - 1);

        // remap IGNORE_LABEL (-1) -> 0
        const int town = tv[k];
        const int tt = (town == -1) ? 0 : town;

        int hs;
        if (x == jj && y == i) {
            // common case for this data (offsets in [0,1)): gather is identity
            hs = tt;
        } else {
            const int g = __ldg(tbase + (y << W_SHIFT) + x);
            hs = (g == -1) ? 0 : g;
        }

        const float f = fv[k];
        const float arg = ((tt == hs) ? f : (1.0f - f)) + EPSF;
        acc -= __logf(arg);
    }

    // Warp reduction
#pragma unroll
    for (int off = 16; off > 0; off >>= 1)
        acc += __shfl_xor_sync(0xFFFFFFFFu, acc, off);

    // Block reduction via shared memory
    __shared__ float warp_sums[THREADS / 32];
    const int lane = threadIdx.x & 31;
    const int wid  = threadIdx.x >> 5;
    if (lane == 0) warp_sums[wid] = acc;
    __syncthreads();

    if (wid == 0) {
        float s = (lane < THREADS / 32) ? warp_sums[lane] : 0.0f;
#pragma unroll
        for (int off = 4; off > 0; off >>= 1)
            s += __shfl_xor_sync(0xFFFFFFFFu, s, off);
        if (lane == 0) {
            // fold W_F * mean: divide by B*H*W
            atomicAdd(out, s * (1.0f / (float)TOTAL_PIX));
        }
    }
}

extern "C" void kernel_launch(void* const* d_in, const int* in_sizes, int n_in,
                              void* d_out, int out_size) {
    const float* o_f    = (const float*)d_in[0];
    const int*   target = (const int*)d_in[1];
    float*       out    = (float*)d_out;

    zero_out_kernel<<<1, 32>>>(out);
    confidence_loss_kernel<<<BLOCKS, THREADS>>>(o_f, target, out);
}